// round 6
// baseline (speedup 1.0000x reference)
#include <cuda_runtime.h>

#define NS 512   // samples
#define DE 512   // embedding dim
#define NC 5     // classes
#define KSPLIT 8
#define KCHUNK (DE / KSPLIT)   // 64

// ---------------- device scratch (no allocation allowed) ----------------
__device__ float g_part[KSPLIT][NS * NS];  // raw partial dot products (8 MB)
__device__ float g_rn[NS];                 // 1 / max(row_norm, 1e-8)
__device__ float g_sum;                    // global loss sum
__device__ int   g_nz;                     // global nonzero count
__device__ int   g_done;                   // completed loss blocks

// ---------------- f32x2 packed helpers (sm_103a) ----------------
__device__ __forceinline__ unsigned long long dupf(float a) {
    unsigned long long d;
    asm("mov.b64 %0, {%1, %1};" : "=l"(d) : "f"(a));
    return d;
}
__device__ __forceinline__ unsigned long long fma2(unsigned long long a,
                                                   unsigned long long b,
                                                   unsigned long long c) {
    unsigned long long d;
    asm("fma.rn.f32x2 %0, %1, %2, %3;" : "=l"(d) : "l"(a), "l"(b), "l"(c));
    return d;
}
__device__ __forceinline__ float2 unpk(unsigned long long v) {
    float2 r;
    asm("mov.b64 {%0, %1}, %2;" : "=f"(r.x), "=f"(r.y) : "l"(v));
    return r;
}

// ---------------- kernel 1: reciprocal row norms + accumulator reset ----------------
__global__ void __launch_bounds__(128) norm_kernel(const float* __restrict__ x) {
    int r = blockIdx.x;
    if (r == 0 && threadIdx.x == 0) {
        g_sum = 0.f; g_nz = 0; g_done = 0;   // re-zeroed on every graph replay
    }
    const float4* row = (const float4*)(x + (size_t)r * DE);
    float s = 0.f;
    for (int j = threadIdx.x; j < DE / 4; j += 128) {
        float4 v = row[j];
        s += v.x * v.x + v.y * v.y + v.z * v.z + v.w * v.w;
    }
    for (int o = 16; o > 0; o >>= 1) s += __shfl_down_sync(0xffffffffu, s, o);
    __shared__ float ws[4];
    int wid = threadIdx.x >> 5, lid = threadIdx.x & 31;
    if (lid == 0) ws[wid] = s;
    __syncthreads();
    if (threadIdx.x == 0) {
        float nrm = sqrtf(ws[0] + ws[1] + ws[2] + ws[3]);
        g_rn[r] = 1.0f / fmaxf(nrm, 1e-8f);
    }
}

// ---------------- kernel 2: partial-K raw dot GEMM ----------------
// 32x32 output tile, 64 threads, 4x4 micro-tile, f32x2 FMA.
// blockIdx.z selects K-chunk [z*64, z*64+64); partial written to g_part[z].
__global__ void __launch_bounds__(64) gemm_kernel(const float* __restrict__ x) {
    __shared__ __align__(16) float As[32][36];  // [k][row]
    __shared__ __align__(16) float Bs[32][36];

    int t = threadIdx.x;           // 0..63
    int bi = blockIdx.y * 32;
    int bj = blockIdx.x * 32;
    int z = blockIdx.z;
    int tx = t & 7, ty = t >> 3;   // 8x8 micro grid
    int lrow = t >> 1;             // 0..31
    int lsel = t & 1;

    unsigned long long acc[4][2];
    #pragma unroll
    for (int r = 0; r < 4; r++) { acc[r][0] = 0ull; acc[r][1] = 0ull; }

    int kbeg = z * KCHUNK;
    #pragma unroll
    for (int k0 = kbeg; k0 < kbeg + KCHUNK; k0 += 32) {
        float4 a[4], b[4];
        const float4* gA = (const float4*)(x + (size_t)(bi + lrow) * DE + k0);
        const float4* gB = (const float4*)(x + (size_t)(bj + lrow) * DE + k0);
        #pragma unroll
        for (int q = 0; q < 4; q++) {
            a[q] = gA[lsel + 2 * q];
            b[q] = gB[lsel + 2 * q];
        }
        __syncthreads();
        #pragma unroll
        for (int q = 0; q < 4; q++) {
            int c = 4 * (lsel + 2 * q);
            As[c + 0][lrow] = a[q].x; As[c + 1][lrow] = a[q].y;
            As[c + 2][lrow] = a[q].z; As[c + 3][lrow] = a[q].w;
            Bs[c + 0][lrow] = b[q].x; Bs[c + 1][lrow] = b[q].y;
            Bs[c + 2][lrow] = b[q].z; Bs[c + 3][lrow] = b[q].w;
        }
        __syncthreads();
        #pragma unroll
        for (int kk = 0; kk < 32; kk++) {
            float4 av = *(const float4*)&As[kk][4 * ty];
            ulonglong2 bv = *(const ulonglong2*)&Bs[kk][4 * tx];
            unsigned long long a0 = dupf(av.x), a1 = dupf(av.y);
            unsigned long long a2 = dupf(av.z), a3 = dupf(av.w);
            acc[0][0] = fma2(a0, bv.x, acc[0][0]); acc[0][1] = fma2(a0, bv.y, acc[0][1]);
            acc[1][0] = fma2(a1, bv.x, acc[1][0]); acc[1][1] = fma2(a1, bv.y, acc[1][1]);
            acc[2][0] = fma2(a2, bv.x, acc[2][0]); acc[2][1] = fma2(a2, bv.y, acc[2][1]);
            acc[3][0] = fma2(a3, bv.x, acc[3][0]); acc[3][1] = fma2(a3, bv.y, acc[3][1]);
        }
    }

    float* dst = g_part[z];
    #pragma unroll
    for (int r = 0; r < 4; r++) {
        float2 p0 = unpk(acc[r][0]);
        float2 p1 = unpk(acc[r][1]);
        float4 o;
        o.x = p0.x; o.y = p0.y; o.z = p1.x; o.w = p1.y;
        *(float4*)&dst[(size_t)(bi + 4 * ty + r) * NS + bj + 4 * tx] = o;
    }
}

// ---------------- kernel 3: per-anchor loss + fused global finalize ----------------
// one block per anchor i, 128 threads; thread t owns columns [4t, 4t+4)
__global__ void __launch_bounds__(128) loss_kernel(const float* __restrict__ dist_raw,
                                                   const int* __restrict__ target,
                                                   float* __restrict__ out) {
    __shared__ __align__(16) float bvals[NS];  // cos[i,j]+margin, or -1e30
    __shared__ float crow[NS];
    __shared__ float cps[NS];
    __shared__ int klist[NS];
    __shared__ float cls_pos[NC];
    __shared__ int kcnt, scount;
    __shared__ float red_s[4];
    __shared__ int red_n[4];

    int i = blockIdx.x;
    int t = threadIdx.x;

    if (t == 0) {
        kcnt = 0; scount = 0;
        float c = 0.f;
        cls_pos[0] = 0.f;
        #pragma unroll
        for (int q = 0; q < NC - 1; q++) {
            c += log1pf(expf(dist_raw[q]));  // softplus cumsum
            cls_pos[q + 1] = c;
        }
    }
    __syncthreads();

    // cos row i: sum 8 K-partials, scale by rn_i*rn_j
    float ri = g_rn[i];
    {
        size_t off = (size_t)i * NS + 4 * t;
        float sx = 0.f, sy = 0.f, sz = 0.f, sw = 0.f;
        #pragma unroll
        for (int z = 0; z < KSPLIT; z++) {
            float4 p = *(const float4*)&g_part[z][off];
            sx += p.x; sy += p.y; sz += p.z; sw += p.w;
        }
        float4 rj = *(const float4*)&g_rn[4 * t];
        float4 c;
        c.x = sx * ri * rj.x;
        c.y = sy * ri * rj.y;
        c.z = sz * ri * rj.z;
        c.w = sw * ri * rj.w;
        *(float4*)&crow[4 * t] = c;
        int4 tg = *(const int4*)&target[4 * t];
        cps[4 * t + 0] = cls_pos[tg.x];
        cps[4 * t + 1] = cls_pos[tg.y];
        cps[4 * t + 2] = cls_pos[tg.z];
        cps[4 * t + 3] = cls_pos[tg.w];
    }
    __syncthreads();

    float cpi = cps[i];
    int myc = 0;
    #pragma unroll
    for (int q = 0; q < 4; q++) {
        int j = 4 * t + q;
        float m = fabsf(cpi - cps[j]);
        bool same = (m == 0.0f);  // class_pos strictly increasing -> equality iff same class
        bvals[j] = same ? -1e30f : (crow[j] + m);
        if (same) {
            myc++;
            if (j != i) klist[atomicAdd(&kcnt, 1)] = j;
        }
    }
    atomicAdd(&scount, myc);
    __syncthreads();

    int nk = kcnt;
    int negc = NS - scount;
    float inv = 1.0f / (float)(negc > 1 ? negc : 1);

    float lsum = 0.f;
    int lnz = 0;
    const float4* bv4 = (const float4*)bvals;
    for (int p = t; p < nk; p += 128) {
        float cik = crow[klist[p]];
        float acc0 = 0.f, acc1 = 0.f;
        #pragma unroll 8
        for (int jj = 0; jj < NS / 4; jj++) {
            float4 bv = bv4[jj];
            acc0 += fmaxf(bv.x - cik, 0.f) + fmaxf(bv.y - cik, 0.f);
            acc1 += fmaxf(bv.z - cik, 0.f) + fmaxf(bv.w - cik, 0.f);
        }
        float acc = acc0 + acc1;
        lsum += acc * inv;
        lnz += (acc != 0.f) ? 1 : 0;
    }

    // block reduce (4 warps)
    for (int o = 16; o > 0; o >>= 1) {
        lsum += __shfl_down_sync(0xffffffffu, lsum, o);
        lnz += __shfl_down_sync(0xffffffffu, lnz, o);
    }
    int wid = t >> 5, lid = t & 31;
    if (lid == 0) { red_s[wid] = lsum; red_n[wid] = lnz; }
    __syncthreads();

    // fused finalize: last block to finish computes the output
    if (t == 0) {
        float bs = red_s[0] + red_s[1] + red_s[2] + red_s[3];
        int bn = red_n[0] + red_n[1] + red_n[2] + red_n[3];
        atomicAdd(&g_sum, bs);
        atomicAdd(&g_nz, bn);
        __threadfence();
        if (atomicAdd(&g_done, 1) == NS - 1) {
            __threadfence();
            float S = atomicAdd(&g_sum, 0.0f);   // atomic read after all adds visible
            int N = atomicAdd(&g_nz, 0);
            out[0] = S / (float)(N > 1 ? N : 1);
        }
    }
}

extern "C" void kernel_launch(void* const* d_in, const int* in_sizes, int n_in,
                              void* d_out, int out_size) {
    const float* pred = (const float*)d_in[0];   // [512, 512] f32
    const float* draw = (const float*)d_in[1];   // [4] f32
    const int* target = (const int*)d_in[2];     // [512] i32
    float* out = (float*)d_out;

    norm_kernel<<<NS, 128>>>(pred);
    gemm_kernel<<<dim3(16, 16, KSPLIT), 64>>>(pred);
    loss_kernel<<<NS, 128>>>(draw, target, out);
}